// round 4
// baseline (speedup 1.0000x reference)
#include <cuda_runtime.h>
#include <cuda_bf16.h>

#define T_LEN 2048
#define KP    17
#define KPAD  18
#define HID   64
#define B_SZ  32
#define NCLS  10
#define TILE_T 16
#define NT    (T_LEN / TILE_T)     // 128

typedef unsigned long long ull;

// Scratch (allocation-free rule: __device__ globals)
__device__ float g_buf0[(size_t)B_SZ * T_LEN * KP * HID];
__device__ float g_buf1[(size_t)B_SZ * T_LEN * KP * HID];
__device__ float g_Wf[3][3 * HID * HID];   // [blk][(tau*CIN + j)*64 + o]
__device__ float g_beta[3][HID];
__device__ float g_part[(size_t)B_SZ * NT * HID];

__device__ __forceinline__ void fma2(ull& d, ull a, ull b) {
    asm("fma.rn.f32x2 %0, %1, %2, %3;" : "=l"(d) : "l"(a), "l"(b), "l"(d));
}
__device__ __forceinline__ ull pack2(float x, float y) {
    ull r;
    asm("mov.b64 %0, {%1, %2};" : "=l"(r) : "f"(x), "f"(y));
    return r;
}
__device__ __forceinline__ float2 unpack2(ull v) {
    float2 r;
    asm("mov.b64 {%0, %1}, %2;" : "=f"(r.x), "=f"(r.y) : "l"(v));
    return r;
}

// ---------------------------------------------------------------------------
// Wf[blk][tau][j][o] = (sum_i gw[j,i] * tw[o,i,tau]) * bn_inv[o]
// beta[blk][o] = bb - bs*bm/sqrt(bv+eps)
// ---------------------------------------------------------------------------
__global__ void prep_kernel(const float* __restrict__ gw0, const float* __restrict__ gw1,
                            const float* __restrict__ gw2, const float* __restrict__ tcn,
                            const float* __restrict__ bs, const float* __restrict__ bb,
                            const float* __restrict__ bm, const float* __restrict__ bv)
{
    int blk = blockIdx.x;      // 0..2
    int tau = blockIdx.y;      // 0..2
    int o   = threadIdx.x;     // 0..63
    const float* gw = (blk == 0) ? gw0 : ((blk == 1) ? gw1 : gw2);
    int CIN = (blk == 0) ? 3 : 64;
    float rstd = rsqrtf(bv[blk*64 + o] + 1e-5f);
    float inv  = bs[blk*64 + o] * rstd;
    if (tau == 0)
        g_beta[blk][o] = bb[blk*64 + o] - bs[blk*64 + o] * bm[blk*64 + o] * rstd;
    const float* tw = tcn + (size_t)blk * HID * HID * 3;   // [o][i][tau]
    for (int j = 0; j < CIN; j++) {
        float s = 0.f;
        for (int i = 0; i < HID; i++)
            s += gw[j*HID + i] * tw[(o*HID + i)*3 + tau];
        g_Wf[blk][(tau*CIN + j)*HID + o] = s * inv;
    }
}

// ---------------------------------------------------------------------------
// Fused ST-GCN block:
//  premix xg = A*x into smem (graph conv commuted to input side),
//  temporal/channel GEMM with f32x2 packed FFMA (rows pairwise in lanes),
//  epilogue: BN bias + ReLU + residual (re-read x from gmem) + optional pool.
// Padded planes: 18 slots per t (slot 17 zero, outputs there discarded).
// ---------------------------------------------------------------------------
template<int CIN, int D, bool RES, bool ACC>
__global__ __launch_bounds__(288, 2)
void stblock(const float* __restrict__ xin, float* __restrict__ yout,
             const float* __restrict__ adjg, int blk)
{
    constexpr int NTT  = TILE_T + 2*D;          // halo'd t rows
    constexpr int NTHP = NTT * KPAD;            // padded plane count
    constexpr int XW   = NTHP + 2;              // even stride per channel
    constexpr int XS   = ((CIN*XW + 3) & ~3);   // 16B-align the Ws region
    constexpr int WS_SZ = (CIN == 64) ? (HID*HID) : (3*CIN*HID);

    extern __shared__ float sm[];
    float* xg   = sm;                    // [CIN][XW] graph-premixed x (padded planes)
    float* Ws   = sm + XS;               // staged weights (per-tau for CIN=64)
    float* sadj = Ws + WS_SZ;            // [17][18], col 17 = 0 (+2 pad)
    float* sbet = sadj + 308;            // [64]

    const int tid = threadIdx.x;
    const int b   = blockIdx.y;
    const int t0  = blockIdx.x * TILE_T;

    for (int u = tid; u < KP*KPAD; u += 288) {
        int v = u / KPAD, k = u - v*KPAD;
        sadj[u] = (k < KP) ? adjg[v*KP + k] : 0.f;
    }
    if (tid < HID) sbet[tid] = g_beta[blk][tid];
    if (CIN == 3) {
        for (int u = tid; u < WS_SZ; u += 288) Ws[u] = g_Wf[blk][u];
    }
    __syncthreads();

    // ---- premix: xg[c][tl*18+k] = sum_v x[tg][v][c] * adj[v][k]  (0 if OOB) ----
    const float* xb = xin + (size_t)b * T_LEN * KP * CIN;
    for (int u = tid; u < NTT * CIN; u += 288) {
        int tl = u / CIN, c = u - tl*CIN;       // consecutive tid -> consecutive c
        int tg = t0 + tl - D;
        float raw[KP];
        if (tg >= 0 && tg < T_LEN) {
            const float* xr = xb + (size_t)tg * KP * CIN + c;
            #pragma unroll
            for (int v = 0; v < KP; v++) raw[v] = __ldg(xr + v*CIN);
        } else {
            #pragma unroll
            for (int v = 0; v < KP; v++) raw[v] = 0.f;
        }
        ull s2[KPAD/2];
        #pragma unroll
        for (int p = 0; p < KPAD/2; p++) s2[p] = 0ull;
        #pragma unroll
        for (int v = 0; v < KP; v++) {
            ull rd = pack2(raw[v], raw[v]);
            const ull* ap = (const ull*)(sadj + v*KPAD);
            #pragma unroll
            for (int p = 0; p < KPAD/2; p++) fma2(s2[p], rd, ap[p]);
        }
        ull* xo = (ull*)(xg + c*XW + tl*KPAD);
        #pragma unroll
        for (int p = 0; p < KPAD/2; p++) xo[p] = s2[p];
    }
    __syncthreads();

    const int cg = tid & 7;          // col group (8 cols each)
    const int rg = tid >> 3;         // padded-row group 0..35
    const int r0 = rg * 8;
    const float* wf = g_Wf[blk];

    ull acc[4][8];                   // [rowpair][col], rows packed in f32x2 lanes
    #pragma unroll
    for (int q = 0; q < 4; q++)
        #pragma unroll
        for (int p = 0; p < 8; p++) acc[q][p] = 0ull;

    #pragma unroll
    for (int tau = 0; tau < 3; tau++) {
        const float* wsrc;
        if (CIN == 64) {
            if (tau > 0) __syncthreads();
            const float4* src = (const float4*)(wf + tau*HID*HID);
            for (int u = tid; u < HID*HID/4; u += 288) ((float4*)Ws)[u] = src[u];
            __syncthreads();
            wsrc = Ws;
        } else {
            wsrc = Ws + tau*CIN*HID;
        }
        const float* xpb = xg + tau*(KPAD*D) + r0;
        #pragma unroll 8
        for (int j = 0; j < CIN; j++) {
            const ull* xp = (const ull*)(xpb + j*XW);
            ull x0 = xp[0], x1 = xp[1], x2 = xp[2], x3 = xp[3];
            const float* wr = wsrc + j*HID + cg*8;
            float4 wa = *(const float4*)(wr);
            float4 wb = *(const float4*)(wr + 4);
            ull wd[8];
            wd[0] = pack2(wa.x, wa.x); wd[1] = pack2(wa.y, wa.y);
            wd[2] = pack2(wa.z, wa.z); wd[3] = pack2(wa.w, wa.w);
            wd[4] = pack2(wb.x, wb.x); wd[5] = pack2(wb.y, wb.y);
            wd[6] = pack2(wb.z, wb.z); wd[7] = pack2(wb.w, wb.w);
            #pragma unroll
            for (int p = 0; p < 8; p++) {
                fma2(acc[0][p], x0, wd[p]);
                fma2(acc[1][p], x1, wd[p]);
                fma2(acc[2][p], x2, wd[p]);
                fma2(acc[3][p], x3, wd[p]);
            }
        }
    }
    __syncthreads();   // Ws reads done (red reuse below); uniform

    // ---- epilogue: bias + relu + residual + store (+pool) ----
    const float4 bA = *(const float4*)(sbet + cg*8);
    const float4 bB = *(const float4*)(sbet + cg*8 + 4);
    float csum[8];
    if (ACC) {
        #pragma unroll
        for (int p = 0; p < 8; p++) csum[p] = 0.f;
    }
    #pragma unroll
    for (int q = 0; q < 4; q++) {
        float vr[2][8];
        #pragma unroll
        for (int p = 0; p < 8; p++) {
            float2 u2 = unpack2(acc[q][p]);
            vr[0][p] = u2.x; vr[1][p] = u2.y;
        }
        #pragma unroll
        for (int h = 0; h < 2; h++) {
            int r  = r0 + 2*q + h;
            int tl = r / KPAD;
            int kk = r - tl*KPAD;
            if (kk < KP) {
                size_t base = (((size_t)b*T_LEN + (t0 + tl))*KP + kk)*HID + cg*8;
                float4 o0, o1;
                o0.x = fmaxf(vr[h][0] + bA.x, 0.f);
                o0.y = fmaxf(vr[h][1] + bA.y, 0.f);
                o0.z = fmaxf(vr[h][2] + bA.z, 0.f);
                o0.w = fmaxf(vr[h][3] + bA.w, 0.f);
                o1.x = fmaxf(vr[h][4] + bB.x, 0.f);
                o1.y = fmaxf(vr[h][5] + bB.y, 0.f);
                o1.z = fmaxf(vr[h][6] + bB.z, 0.f);
                o1.w = fmaxf(vr[h][7] + bB.w, 0.f);
                if (RES) {
                    float4 x0 = *(const float4*)(xin + base);
                    float4 x1 = *(const float4*)(xin + base + 4);
                    o0.x += x0.x; o0.y += x0.y; o0.z += x0.z; o0.w += x0.w;
                    o1.x += x1.x; o1.y += x1.y; o1.z += x1.z; o1.w += x1.w;
                }
                *(float4*)(yout + base)     = o0;
                *(float4*)(yout + base + 4) = o1;
                if (ACC) {
                    csum[0] += o0.x; csum[1] += o0.y; csum[2] += o0.z; csum[3] += o0.w;
                    csum[4] += o1.x; csum[5] += o1.y; csum[6] += o1.z; csum[7] += o1.w;
                }
            }
        }
    }
    if (ACC) {
        float* red = Ws;    // reuse; 36*64 = 2304 <= 4096 floats
        *(float4*)(red + rg*64 + cg*8)     = make_float4(csum[0], csum[1], csum[2], csum[3]);
        *(float4*)(red + rg*64 + cg*8 + 4) = make_float4(csum[4], csum[5], csum[6], csum[7]);
        __syncthreads();
        if (tid < 64) {
            float s = 0.f;
            #pragma unroll 4
            for (int m = 0; m < 36; m++) s += red[m*64 + tid];
            g_part[((size_t)b*NT + blockIdx.x)*64 + tid] = s;
        }
    }
}

// ---------------------------------------------------------------------------
// Final: mean-pool (from partials) -> LayerNorm -> FC
// ---------------------------------------------------------------------------
__global__ void finalize_kernel(const float* __restrict__ lns, const float* __restrict__ lnb,
                                const float* __restrict__ fcw, const float* __restrict__ fcb,
                                float* __restrict__ out)
{
    int b = blockIdx.x;
    int c = threadIdx.x;   // 64 threads
    float s = 0.f;
    const float* pp = g_part + (size_t)b * NT * 64;
    for (int t = 0; t < NT; t++) s += pp[t*64 + c];
    s *= (1.f / ((float)T_LEN * (float)KP));

    __shared__ float red[64];
    __shared__ float sf[64];
    red[c] = s; __syncthreads();
    for (int off = 32; off; off >>= 1) { if (c < off) red[c] += red[c+off]; __syncthreads(); }
    float mu = red[0] * (1.f/64.f);
    __syncthreads();
    float d = s - mu;
    red[c] = d * d; __syncthreads();
    for (int off = 32; off; off >>= 1) { if (c < off) red[c] += red[c+off]; __syncthreads(); }
    float var = red[0] * (1.f/64.f);
    float f = d * rsqrtf(var + 1e-5f) * lns[c] + lnb[c];
    sf[c] = f; __syncthreads();
    if (c < NCLS) {
        float o = fcb[c];
        #pragma unroll
        for (int i = 0; i < 64; i++) o += sf[i] * fcw[i*NCLS + c];
        out[b*NCLS + c] = o;
    }
}

static inline size_t smem_bytes(int CIN, int D) {
    int NTT = TILE_T + 2*D;
    int XW  = NTT*KPAD + 2;
    int XS  = ((CIN*XW + 3) & ~3);
    int WS  = (CIN == 64) ? (HID*HID) : (3*CIN*HID);
    return (size_t)(XS + WS + 308 + 64) * sizeof(float);
}

extern "C" void kernel_launch(void* const* d_in, const int* in_sizes, int n_in,
                              void* d_out, int out_size)
{
    const float* kpts = (const float*)d_in[0];
    const float* adj  = (const float*)d_in[1];
    const float* gw0  = (const float*)d_in[2];
    const float* gw1  = (const float*)d_in[3];
    const float* gw2  = (const float*)d_in[4];
    const float* tcn  = (const float*)d_in[5];
    const float* bs   = (const float*)d_in[6];
    const float* bb   = (const float*)d_in[7];
    const float* bm   = (const float*)d_in[8];
    const float* bv   = (const float*)d_in[9];
    const float* lns  = (const float*)d_in[10];
    const float* lnb  = (const float*)d_in[11];
    const float* fcw  = (const float*)d_in[12];
    const float* fcb  = (const float*)d_in[13];
    float* out = (float*)d_out;

    float *buf0, *buf1;
    cudaGetSymbolAddress((void**)&buf0, g_buf0);
    cudaGetSymbolAddress((void**)&buf1, g_buf1);

    size_t s0 = smem_bytes(3, 1);
    size_t s1 = smem_bytes(64, 1);
    size_t s2 = smem_bytes(64, 2);
    cudaFuncSetAttribute(stblock<3,1,false,false>, cudaFuncAttributeMaxDynamicSharedMemorySize, (int)s0);
    cudaFuncSetAttribute(stblock<64,1,true,false>, cudaFuncAttributeMaxDynamicSharedMemorySize, (int)s1);
    cudaFuncSetAttribute(stblock<64,2,true,true>,  cudaFuncAttributeMaxDynamicSharedMemorySize, (int)s2);

    prep_kernel<<<dim3(3,3), 64>>>(gw0, gw1, gw2, tcn, bs, bb, bm, bv);

    dim3 grid(NT, B_SZ);
    stblock<3,1,false,false><<<grid, 288, s0>>>(kpts, buf0, adj, 0);
    stblock<64,1,true,false><<<grid, 288, s1>>>(buf0, buf1, adj, 1);
    stblock<64,2,true,true> <<<grid, 288, s2>>>(buf1, buf0, adj, 2);

    finalize_kernel<<<B_SZ, 64>>>(lns, lnb, fcw, fcb, out);
}

// round 6
// speedup vs baseline: 1.7832x; 1.7832x over previous
#include <cuda_runtime.h>
#include <cuda_bf16.h>
#include <cstdint>

#define T_LEN 2048
#define KP    17
#define KPAD  18
#define HID   64
#define B_SZ  32
#define NCLS  10
#define TILE_T 16
#define NT    (T_LEN / TILE_T)
#define RPB   (T_LEN * KP)            // 34816 flat rows per batch (= 272*128)
#define TILES_PB (RPB / 128)          // 272
#define NTILES (TILES_PB * B_SZ)      // 8704
#define PAD   64
#define PADROWS (RPB + 2*PAD)
#define KWPAD 100                     // 96 B-words + 4 pad (conflict-free ldmatrix)
#define SMEM_MMA (2*64*KWPAD*4 + 256)

typedef unsigned long long ull;

__device__ float    g_buf0[(size_t)B_SZ * RPB * HID];
__device__ float    g_buf1[(size_t)B_SZ * RPB * HID];
__device__ uint32_t g_xh[(size_t)B_SZ * PADROWS * 32];
__device__ uint32_t g_xl[(size_t)B_SZ * PADROWS * 32];
__device__ float    g_Wf[3][3 * HID * HID];
__device__ unsigned short g_Wh[2][64 * 192];   // [o][k] row-major (k = tau*64+j)
__device__ unsigned short g_Wl[2][64 * 192];
__device__ float    g_beta[3][HID];
__device__ int      g_nnz[KP];
__device__ int      g_vidx[KP][KP];
__device__ float    g_vw[KP][KP];
__device__ float    g_part[(size_t)NTILES * 64];

// ---------------- helpers ---------------------------------------------------
__device__ __forceinline__ void fma2(ull& d, ull a, ull b) {
    asm("fma.rn.f32x2 %0, %1, %2, %3;" : "=l"(d) : "l"(a), "l"(b), "l"(d));
}
__device__ __forceinline__ ull pack2(float x, float y) {
    ull r; asm("mov.b64 %0, {%1, %2};" : "=l"(r) : "f"(x), "f"(y)); return r;
}
__device__ __forceinline__ float2 unpack2(ull v) {
    float2 r; asm("mov.b64 {%0, %1}, %2;" : "=f"(r.x), "=f"(r.y) : "l"(v)); return r;
}
__device__ __forceinline__ uint32_t s2u(const void* p) {
    uint32_t a;
    asm("{ .reg .u64 t; cvta.to.shared.u64 t, %1; cvt.u32.u64 %0, t; }" : "=r"(a) : "l"(p));
    return a;
}
__device__ __forceinline__ void ldm4(uint32_t* r, uint32_t addr) {
    asm volatile("ldmatrix.sync.aligned.m8n8.x4.shared.b16 {%0,%1,%2,%3}, [%4];"
        : "=r"(r[0]), "=r"(r[1]), "=r"(r[2]), "=r"(r[3]) : "r"(addr));
}
__device__ __forceinline__ void mma_bf16(float* d, const uint32_t* a, uint32_t b0, uint32_t b1) {
    asm volatile("mma.sync.aligned.m16n8k16.row.col.f32.bf16.bf16.f32 "
        "{%0,%1,%2,%3}, {%4,%5,%6,%7}, {%8,%9}, {%0,%1,%2,%3};"
        : "+f"(d[0]), "+f"(d[1]), "+f"(d[2]), "+f"(d[3])
        : "r"(a[0]), "r"(a[1]), "r"(a[2]), "r"(a[3]), "r"(b0), "r"(b1));
}

// ---------------------------------------------------------------------------
// prep: BN-folded fused weights, bf16 hi/lo weight split (layers 1,2), CSR adj
// ---------------------------------------------------------------------------
__global__ void prep_kernel(const float* __restrict__ adj,
                            const float* __restrict__ gw0, const float* __restrict__ gw1,
                            const float* __restrict__ gw2, const float* __restrict__ tcn,
                            const float* __restrict__ bs, const float* __restrict__ bb,
                            const float* __restrict__ bm, const float* __restrict__ bv)
{
    int blk = blockIdx.x, tau = blockIdx.y, o = threadIdx.x;
    const float* gw = (blk == 0) ? gw0 : ((blk == 1) ? gw1 : gw2);
    int CIN = (blk == 0) ? 3 : 64;
    float rstd = rsqrtf(bv[blk*64 + o] + 1e-5f);
    float inv  = bs[blk*64 + o] * rstd;
    if (tau == 0)
        g_beta[blk][o] = bb[blk*64 + o] - bs[blk*64 + o] * bm[blk*64 + o] * rstd;
    if (blk == 0 && tau == 0 && o < KP) {
        int n = 0;
        for (int v = 0; v < KP; v++) {
            float w = adj[v*KP + o];
            if (w != 0.f) { g_vidx[o][n] = v; g_vw[o][n] = w; n++; }
        }
        g_nnz[o] = n;
    }
    const float* tw = tcn + (size_t)blk * HID * HID * 3;
    for (int j = 0; j < CIN; j++) {
        float s = 0.f;
        for (int i = 0; i < HID; i++)
            s += gw[j*HID + i] * tw[(o*HID + i)*3 + tau];
        float val = s * inv;
        g_Wf[blk][(tau*CIN + j)*HID + o] = val;
        if (blk >= 1) {
            __nv_bfloat16 h = __float2bfloat16(val);
            float hf = __bfloat162float(h);
            __nv_bfloat16 l = __float2bfloat16(val - hf);
            int k = tau*64 + j;
            g_Wh[blk-1][o*192 + k] = reinterpret_cast<unsigned short&>(h);
            g_Wl[blk-1][o*192 + k] = reinterpret_cast<unsigned short&>(l);
        }
    }
}

// ---------------------------------------------------------------------------
// premix: xg = A*x (CSR over keypoints), bf16 hi/lo split, word-permuted so
// A-fragment words (t, t+4) land adjacent -> LDG.64 in the mma kernel.
// ---------------------------------------------------------------------------
#define PM_MAIN ((B_SZ * RPB) / 8)
#define PM_PADB ((B_SZ * 2 * PAD) / 8)
__global__ __launch_bounds__(256)
void premix_kernel(const float* __restrict__ x)
{
    int tid = threadIdx.x;
    int rloc = tid >> 5, c2 = tid & 31;
    int s = c2 & 7, g = c2 >> 3;
    int pos = g*8 + (s < 4 ? 2*s : 2*(s-4)+1);
    if (blockIdx.x < PM_MAIN) {
        size_t row = (size_t)blockIdx.x * 8 + rloc;
        int b = (int)(row / RPB);
        int r = (int)(row - (size_t)b * RPB);
        int t = r / KP, k = r - t*KP;
        const float* xb = x + ((size_t)b*RPB + (size_t)t*KP)*64 + c2*2;
        int n = g_nnz[k];
        float ax = 0.f, ay = 0.f;
        for (int i = 0; i < n; i++) {
            float w = g_vw[k][i];
            float2 xv = *(const float2*)(xb + g_vidx[k][i]*64);
            ax = fmaf(w, xv.x, ax);
            ay = fmaf(w, xv.y, ay);
        }
        uint32_t hu;
        asm("cvt.rn.bf16x2.f32 %0, %1, %2;" : "=r"(hu) : "f"(ay), "f"(ax));
        __nv_bfloat162 hb = *reinterpret_cast<__nv_bfloat162*>(&hu);
        float l0 = ax - __bfloat162float(hb.x);
        float l1 = ay - __bfloat162float(hb.y);
        uint32_t lu;
        asm("cvt.rn.bf16x2.f32 %0, %1, %2;" : "=r"(lu) : "f"(l1), "f"(l0));
        size_t pr = (size_t)b*PADROWS + PAD + r;
        g_xh[pr*32 + pos] = hu;
        g_xl[pr*32 + pos] = lu;
    } else {
        int idx = (int)(blockIdx.x - PM_MAIN) * 8 + rloc;
        int b = idx / (2*PAD), o = idx - b*(2*PAD);
        size_t pr = (size_t)b*PADROWS + (o < PAD ? o : (PAD + RPB + (o - PAD)));
        g_xh[pr*32 + c2] = 0u;
        g_xl[pr*32 + c2] = 0u;
    }
}

// ---------------------------------------------------------------------------
// mma.sync GEMM layer: per 128-row tile, C = Ah*Bh + Al*Bh + Ah*Bl (fp32 acc)
// M=128 (4 warps x 32 rows), N=64, K=192. B staged in smem, A via LDG.64.
// ---------------------------------------------------------------------------
template<int SH, bool POOL>
__global__ __launch_bounds__(128)
void mma_kernel(const float* __restrict__ xin, float* __restrict__ yout,
                int wsel, int blk)
{
    extern __shared__ char smem[];
    uint32_t* sBh = (uint32_t*)smem;
    uint32_t* sBl = sBh + 64*KWPAD;
    float* sbias  = (float*)(smem + 2*64*KWPAD*4);

    const int tid  = threadIdx.x;
    const int w    = tid >> 5;
    const int lane = tid & 31;
    const int grp  = lane >> 2;
    const int thr  = lane & 3;

    // stage B (hi+lo) into padded smem rows
    {
        const uint32_t* wh32 = (const uint32_t*)g_Wh[wsel];
        const uint32_t* wl32 = (const uint32_t*)g_Wl[wsel];
        for (int u = tid; u < 64*96; u += 128) {
            int n = u / 96, kw = u - n*96;
            sBh[n*KWPAD + kw] = wh32[u];
            sBl[n*KWPAD + kw] = wl32[u];
        }
        if (tid < 64) sbias[tid] = g_beta[blk][tid];
    }
    __syncthreads();

    const int tile = blockIdx.x;
    const int b    = tile / TILES_PB;
    const int rloc = (tile - b*TILES_PB)*128 + w*32 + grp;   // local row (mi=0, lo)
    const long long prow0 = (long long)b*PADROWS + PAD + rloc;

    const uint32_t sb = s2u(smem);
    const int rowsel = (lane & 7) + ((lane >> 4) << 3);
    const int kq     = ((lane >> 3) & 1) * 4;
    const uint32_t bAH = sb + (uint32_t)(rowsel*KWPAD + kq)*4;
    const uint32_t bAL = bAH + 64*KWPAD*4;

    float C[2][8][4];
    #pragma unroll
    for (int mi = 0; mi < 2; mi++)
        #pragma unroll
        for (int nf = 0; nf < 8; nf++)
            #pragma unroll
            for (int q = 0; q < 4; q++) C[mi][nf][q] = 0.f;

    #pragma unroll
    for (int ti = 0; ti < 3; ti++) {
        const long long pa0 = (prow0 + (long long)(ti - 1)*SH) * 32;
        #pragma unroll
        for (int ks = 0; ks < 4; ks++) {
            uint32_t ah[2][4], al[2][4];
            #pragma unroll
            for (int mi = 0; mi < 2; mi++) {
                long long pa = pa0 + mi*512 + ks*8 + thr*2;
                uint2 h0 = *(const uint2*)(g_xh + pa);
                uint2 h1 = *(const uint2*)(g_xh + pa + 256);
                ah[mi][0] = h0.x; ah[mi][2] = h0.y;
                ah[mi][1] = h1.x; ah[mi][3] = h1.y;
                uint2 l0 = *(const uint2*)(g_xl + pa);
                uint2 l1 = *(const uint2*)(g_xl + pa + 256);
                al[mi][0] = l0.x; al[mi][2] = l0.y;
                al[mi][1] = l1.x; al[mi][3] = l1.y;
            }
            const int kstep = ti*4 + ks;
            #pragma unroll
            for (int p = 0; p < 4; p++) {
                uint32_t bh[4], bl[4];
                ldm4(bh, bAH + (uint32_t)(p*16*KWPAD*4 + kstep*32));
                ldm4(bl, bAL + (uint32_t)(p*16*KWPAD*4 + kstep*32));
                #pragma unroll
                for (int mi = 0; mi < 2; mi++) {
                    mma_bf16(C[mi][2*p],   ah[mi], bh[0], bh[1]);
                    mma_bf16(C[mi][2*p+1], ah[mi], bh[2], bh[3]);
                    mma_bf16(C[mi][2*p],   al[mi], bh[0], bh[1]);
                    mma_bf16(C[mi][2*p+1], al[mi], bh[2], bh[3]);
                    mma_bf16(C[mi][2*p],   ah[mi], bl[0], bl[1]);
                    mma_bf16(C[mi][2*p+1], ah[mi], bl[2], bl[3]);
                }
            }
        }
    }

    // ---- epilogue: bias + relu + residual (+pool) ----
    const long long grow_base = (long long)tile*128 + w*32 + grp;
    float csum[16];
    if (POOL) {
        #pragma unroll
        for (int u = 0; u < 16; u++) csum[u] = 0.f;
    }
    #pragma unroll
    for (int mi = 0; mi < 2; mi++) {
        #pragma unroll
        for (int h = 0; h < 2; h++) {
            long long gr = grow_base + mi*16 + h*8;
            const float2* xr = (const float2*)(xin + gr*64);
            float2* yr = (float2*)(yout + gr*64);
            #pragma unroll
            for (int nf = 0; nf < 8; nf++) {
                int c2i = nf*4 + thr;              // float2 index = col/2
                float2 bsv = *(const float2*)(sbias + c2i*2);
                float2 xv = xr[c2i];
                float o0 = fmaxf(C[mi][nf][2*h]   + bsv.x, 0.f) + xv.x;
                float o1 = fmaxf(C[mi][nf][2*h+1] + bsv.y, 0.f) + xv.y;
                if (!POOL) {
                    yr[c2i] = make_float2(o0, o1);
                } else {
                    csum[2*nf]   += o0;
                    csum[2*nf+1] += o1;
                }
            }
        }
    }
    if (POOL) {
        __syncthreads();                 // done reading B
        float* pool = (float*)smem;      // [32][64]
        int prow = w*8 + grp;
        #pragma unroll
        for (int nf = 0; nf < 8; nf++)
            *(float2*)(pool + prow*64 + nf*8 + 2*thr) = make_float2(csum[2*nf], csum[2*nf+1]);
        __syncthreads();
        if (tid < 64) {
            float s = 0.f;
            #pragma unroll 4
            for (int m = 0; m < 32; m++) s += pool[m*64 + tid];
            g_part[(size_t)tile*64 + tid] = s;
        }
    }
}

// ---------------------------------------------------------------------------
// Layer 0 (CIN=3) fp32 f32x2 kernel (proven path)
// ---------------------------------------------------------------------------
__global__ __launch_bounds__(288, 2)
void stblock0(const float* __restrict__ xin, float* __restrict__ yout,
              const float* __restrict__ adjg)
{
    constexpr int CIN = 3, D = 1;
    constexpr int NTT  = TILE_T + 2*D;
    constexpr int XW   = NTT*KPAD + 2;
    constexpr int XS   = ((CIN*XW + 3) & ~3);
    constexpr int WS_SZ = 3*CIN*HID;

    extern __shared__ float sm[];
    float* xg   = sm;
    float* Ws   = sm + XS;
    float* sadj = Ws + WS_SZ;
    float* sbet = sadj + 308;

    const int tid = threadIdx.x;
    const int b   = blockIdx.y;
    const int t0  = blockIdx.x * TILE_T;

    for (int u = tid; u < KP*KPAD; u += 288) {
        int v = u / KPAD, k = u - v*KPAD;
        sadj[u] = (k < KP) ? adjg[v*KP + k] : 0.f;
    }
    if (tid < HID) sbet[tid] = g_beta[0][tid];
    for (int u = tid; u < WS_SZ; u += 288) Ws[u] = g_Wf[0][u];
    __syncthreads();

    const float* xb = xin + (size_t)b * T_LEN * KP * CIN;
    for (int u = tid; u < NTT * CIN; u += 288) {
        int tl = u / CIN, c = u - tl*CIN;
        int tg = t0 + tl - D;
        float raw[KP];
        if (tg >= 0 && tg < T_LEN) {
            const float* xr = xb + (size_t)tg * KP * CIN + c;
            #pragma unroll
            for (int v = 0; v < KP; v++) raw[v] = __ldg(xr + v*CIN);
        } else {
            #pragma unroll
            for (int v = 0; v < KP; v++) raw[v] = 0.f;
        }
        ull s2[KPAD/2];
        #pragma unroll
        for (int p = 0; p < KPAD/2; p++) s2[p] = 0ull;
        #pragma unroll
        for (int v = 0; v < KP; v++) {
            ull rd = pack2(raw[v], raw[v]);
            const ull* ap = (const ull*)(sadj + v*KPAD);
            #pragma unroll
            for (int p = 0; p < KPAD/2; p++) fma2(s2[p], rd, ap[p]);
        }
        ull* xo = (ull*)(xg + c*XW + tl*KPAD);
        #pragma unroll
        for (int p = 0; p < KPAD/2; p++) xo[p] = s2[p];
    }
    __syncthreads();

    const int cg = tid & 7;
    const int rg = tid >> 3;
    const int r0 = rg * 8;

    ull acc[4][8];
    #pragma unroll
    for (int q = 0; q < 4; q++)
        #pragma unroll
        for (int p = 0; p < 8; p++) acc[q][p] = 0ull;

    #pragma unroll
    for (int tau = 0; tau < 3; tau++) {
        const float* wsrc = Ws + tau*CIN*HID;
        const float* xpb = xg + tau*(KPAD*D) + r0;
        #pragma unroll
        for (int j = 0; j < CIN; j++) {
            const ull* xp = (const ull*)(xpb + j*XW);
            ull x0 = xp[0], x1 = xp[1], x2 = xp[2], x3 = xp[3];
            const float* wr = wsrc + j*HID + cg*8;
            float4 wa = *(const float4*)(wr);
            float4 wb = *(const float4*)(wr + 4);
            ull wd[8];
            wd[0] = pack2(wa.x, wa.x); wd[1] = pack2(wa.y, wa.y);
            wd[2] = pack2(wa.z, wa.z); wd[3] = pack2(wa.w, wa.w);
            wd[4] = pack2(wb.x, wb.x); wd[5] = pack2(wb.y, wb.y);
            wd[6] = pack2(wb.z, wb.z); wd[7] = pack2(wb.w, wb.w);
            #pragma unroll
            for (int p = 0; p < 8; p++) {
                fma2(acc[0][p], x0, wd[p]);
                fma2(acc[1][p], x1, wd[p]);
                fma2(acc[2][p], x2, wd[p]);
                fma2(acc[3][p], x3, wd[p]);
            }
        }
    }

    const float4 bA = *(const float4*)(sbet + cg*8);
    const float4 bB = *(const float4*)(sbet + cg*8 + 4);
    #pragma unroll
    for (int q = 0; q < 4; q++) {
        float vr[2][8];
        #pragma unroll
        for (int p = 0; p < 8; p++) {
            float2 u2 = unpack2(acc[q][p]);
            vr[0][p] = u2.x; vr[1][p] = u2.y;
        }
        #pragma unroll
        for (int h = 0; h < 2; h++) {
            int r  = r0 + 2*q + h;
            int tl = r / KPAD;
            int kk = r - tl*KPAD;
            if (kk < KP) {
                size_t base = (((size_t)b*T_LEN + (t0 + tl))*KP + kk)*HID + cg*8;
                float4 o0, o1;
                o0.x = fmaxf(vr[h][0] + bA.x, 0.f);
                o0.y = fmaxf(vr[h][1] + bA.y, 0.f);
                o0.z = fmaxf(vr[h][2] + bA.z, 0.f);
                o0.w = fmaxf(vr[h][3] + bA.w, 0.f);
                o1.x = fmaxf(vr[h][4] + bB.x, 0.f);
                o1.y = fmaxf(vr[h][5] + bB.y, 0.f);
                o1.z = fmaxf(vr[h][6] + bB.z, 0.f);
                o1.w = fmaxf(vr[h][7] + bB.w, 0.f);
                *(float4*)(yout + base)     = o0;
                *(float4*)(yout + base + 4) = o1;
            }
        }
    }
}

// ---------------------------------------------------------------------------
// finalize: mean-pool partials -> LayerNorm -> FC
// ---------------------------------------------------------------------------
__global__ void finalize_kernel(const float* __restrict__ lns, const float* __restrict__ lnb,
                                const float* __restrict__ fcw, const float* __restrict__ fcb,
                                float* __restrict__ out)
{
    int b = blockIdx.x;
    int c = threadIdx.x;
    float s = 0.f;
    const float* pp = g_part + (size_t)b * TILES_PB * 64;
    for (int t = 0; t < TILES_PB; t++) s += pp[t*64 + c];
    s *= (1.f / ((float)T_LEN * (float)KP));

    __shared__ float red[64];
    __shared__ float sf[64];
    red[c] = s; __syncthreads();
    for (int off = 32; off; off >>= 1) { if (c < off) red[c] += red[c+off]; __syncthreads(); }
    float mu = red[0] * (1.f/64.f);
    __syncthreads();
    float d = s - mu;
    red[c] = d * d; __syncthreads();
    for (int off = 32; off; off >>= 1) { if (c < off) red[c] += red[c+off]; __syncthreads(); }
    float var = red[0] * (1.f/64.f);
    float f = d * rsqrtf(var + 1e-5f) * lns[c] + lnb[c];
    sf[c] = f; __syncthreads();
    if (c < NCLS) {
        float o = fcb[c];
        #pragma unroll
        for (int i = 0; i < 64; i++) o += sf[i] * fcw[i*NCLS + c];
        out[b*NCLS + c] = o;
    }
}

extern "C" void kernel_launch(void* const* d_in, const int* in_sizes, int n_in,
                              void* d_out, int out_size)
{
    const float* kpts = (const float*)d_in[0];
    const float* adj  = (const float*)d_in[1];
    const float* gw0  = (const float*)d_in[2];
    const float* gw1  = (const float*)d_in[3];
    const float* gw2  = (const float*)d_in[4];
    const float* tcn  = (const float*)d_in[5];
    const float* bs   = (const float*)d_in[6];
    const float* bb   = (const float*)d_in[7];
    const float* bm   = (const float*)d_in[8];
    const float* bv   = (const float*)d_in[9];
    const float* lns  = (const float*)d_in[10];
    const float* lnb  = (const float*)d_in[11];
    const float* fcw  = (const float*)d_in[12];
    const float* fcb  = (const float*)d_in[13];
    float* out = (float*)d_out;

    float *buf0, *buf1;
    cudaGetSymbolAddress((void**)&buf0, g_buf0);
    cudaGetSymbolAddress((void**)&buf1, g_buf1);

    int NTT = TILE_T + 2, XW = NTT*KPAD + 2;
    size_t s0 = (size_t)(((3*XW + 3) & ~3) + 3*3*HID + 308 + 64) * sizeof(float);
    cudaFuncSetAttribute(stblock0, cudaFuncAttributeMaxDynamicSharedMemorySize, (int)s0);
    cudaFuncSetAttribute(mma_kernel<17,false>, cudaFuncAttributeMaxDynamicSharedMemorySize, SMEM_MMA);
    cudaFuncSetAttribute(mma_kernel<34,true>,  cudaFuncAttributeMaxDynamicSharedMemorySize, SMEM_MMA);

    prep_kernel<<<dim3(3,3), 64>>>(adj, gw0, gw1, gw2, tcn, bs, bb, bm, bv);

    dim3 grid0(NT, B_SZ);
    stblock0<<<grid0, 288, s0>>>(kpts, buf0, adj);

    premix_kernel<<<PM_MAIN + PM_PADB, 256>>>(buf0);
    mma_kernel<17,false><<<NTILES, 128, SMEM_MMA>>>(buf0, buf1, 0, 1);

    premix_kernel<<<PM_MAIN + PM_PADB, 256>>>(buf1);
    mma_kernel<34,true><<<NTILES, 128, SMEM_MMA>>>(buf1, nullptr, 1, 2);

    finalize_kernel<<<B_SZ, 64>>>(lns, lnb, fcw, fcb, out);
}